// round 1
// baseline (speedup 1.0000x reference)
#include <cuda_runtime.h>

// Problem constants
#define BATCH 4
#define SEQ   4096
#define DIM   1024
#define NH    16
#define HD    64
#define NC    8             // split-S chunks for kv accumulation
#define CHUNK (SEQ / NC)    // 512

// ---------------------------------------------------------------------------
// Scratch (static __device__ globals; allocation-free per harness rules)
// ---------------------------------------------------------------------------
__device__ float g_q[BATCH * SEQ * DIM];                 // 64 MB
__device__ float g_k[BATCH * SEQ * DIM];                 // 64 MB
__device__ float g_v[BATCH * SEQ * DIM];                 // 64 MB
__device__ float g_kvp[BATCH * NH * NC * HD * HD];       // 8 MB  (kv partials)
__device__ float g_mt[BATCH * DIM * DIM];                // 16 MB (fused kv@o_w^T, stored [j][k])

__device__ __forceinline__ float* scratch_ptr(int s) {
    switch (s) {
        case 1: return g_q;
        case 2: return g_k;
        case 3: return g_v;
        case 4: return g_mt;
        default: return nullptr;
    }
}

// ---------------------------------------------------------------------------
// GEMM: C[M,N] = A[M,K] * B[N,K]^T + bias[N]   (optional ReLU epilogue)
// A row-major [M,K], B row-major [N,K] (K contiguous in both), C row-major.
// 128x128 block tile, BK=8, 256 threads, 8x8 per thread, double-buffered smem.
// blockIdx.z batches via the given strides.
// ---------------------------------------------------------------------------
template <bool RELU>
__global__ __launch_bounds__(256, 2)
void gemm_bias(const float* __restrict__ Aext, int aSel,
               const float* __restrict__ Bext, int bSel,
               const float* __restrict__ bias,
               float* __restrict__ Cext, int cSel,
               int M, int N, int K,
               long sA, long sB, long sC)
{
    __shared__ float As[2][8][128];
    __shared__ float Bs[2][8][128];

    const float* A = Aext ? Aext : scratch_ptr(aSel);
    const float* B = Bext ? Bext : scratch_ptr(bSel);
    float*       C = Cext ? Cext : scratch_ptr(cSel);

    A += (long)blockIdx.z * sA;
    B += (long)blockIdx.z * sB;
    C += (long)blockIdx.z * sC;

    const int t  = threadIdx.x;
    const int m0 = blockIdx.y * 128;
    const int n0 = blockIdx.x * 128;

    // Global->smem load mapping: each thread loads one float4 of A and of B
    const int lr = t >> 1;          // 0..127 tile row
    const int lk = (t & 1) * 4;     // 0 or 4 within BK=8
    const float* Ag = A + (long)(m0 + lr) * K + lk;
    const float* Bg = B + (long)(n0 + lr) * K + lk;

    // Prologue: fill buffer 0
    {
        float4 a4 = *(const float4*)Ag;
        float4 b4 = *(const float4*)Bg;
        As[0][lk + 0][lr] = a4.x; As[0][lk + 1][lr] = a4.y;
        As[0][lk + 2][lr] = a4.z; As[0][lk + 3][lr] = a4.w;
        Bs[0][lk + 0][lr] = b4.x; Bs[0][lk + 1][lr] = b4.y;
        Bs[0][lk + 2][lr] = b4.z; Bs[0][lk + 3][lr] = b4.w;
    }
    __syncthreads();

    const int tm = (t >> 4) * 8;    // 0..120
    const int tn = (t & 15) * 8;    // 0..120

    float acc[8][8] = {};
    const int nk = K >> 3;
    int buf = 0;

    for (int kt = 0; kt < nk; ++kt) {
        // Prefetch next K-slab into registers while computing on current buffer
        float4 na, nb;
        const bool more = (kt + 1) < nk;
        if (more) {
            na = *(const float4*)(Ag + (kt + 1) * 8);
            nb = *(const float4*)(Bg + (kt + 1) * 8);
        }

        #pragma unroll
        for (int kk = 0; kk < 8; ++kk) {
            float af[8], bf[8];
            *(float4*)(af)     = *(const float4*)&As[buf][kk][tm];
            *(float4*)(af + 4) = *(const float4*)&As[buf][kk][tm + 4];
            *(float4*)(bf)     = *(const float4*)&Bs[buf][kk][tn];
            *(float4*)(bf + 4) = *(const float4*)&Bs[buf][kk][tn + 4];
            #pragma unroll
            for (int i = 0; i < 8; ++i)
                #pragma unroll
                for (int j = 0; j < 8; ++j)
                    acc[i][j] += af[i] * bf[j];
        }

        if (more) {
            buf ^= 1;
            As[buf][lk + 0][lr] = na.x; As[buf][lk + 1][lr] = na.y;
            As[buf][lk + 2][lr] = na.z; As[buf][lk + 3][lr] = na.w;
            Bs[buf][lk + 0][lr] = nb.x; Bs[buf][lk + 1][lr] = nb.y;
            Bs[buf][lk + 2][lr] = nb.z; Bs[buf][lk + 3][lr] = nb.w;
            __syncthreads();
        }
    }

    // Epilogue: bias (+ optional ReLU), vectorized stores
    float bv[8];
    #pragma unroll
    for (int j = 0; j < 8; ++j) bv[j] = bias[n0 + tn + j];

    #pragma unroll
    for (int i = 0; i < 8; ++i) {
        float r[8];
        #pragma unroll
        for (int j = 0; j < 8; ++j) {
            float v = acc[i][j] + bv[j];
            if (RELU) v = fmaxf(v, 0.0f);
            r[j] = v;
        }
        float* cp = C + (long)(m0 + tm + i) * N + n0 + tn;
        *(float4*)(cp)     = make_float4(r[0], r[1], r[2], r[3]);
        *(float4*)(cp + 4) = make_float4(r[4], r[5], r[6], r[7]);
    }
}

// ---------------------------------------------------------------------------
// kv partials: for each (b, h, chunk c):
//   P[b,h,c,d,e] = sum_{s in chunk} k[b,s,h,d] * v[b,s,h,e]
// Deterministic split-S (no atomics). Reads g_k, g_v; writes g_kvp.
// grid = (NC, NH, BATCH), 256 threads; each thread owns a 4x4 of the 64x64.
// ---------------------------------------------------------------------------
__global__ __launch_bounds__(256)
void kv_partial()
{
    __shared__ float ks[64][64];
    __shared__ float vs[64][64];

    const int c = blockIdx.x, h = blockIdx.y, b = blockIdx.z;
    const int t  = threadIdx.x;
    const int td = t >> 4;   // 0..15 -> d block
    const int te = t & 15;   // 0..15 -> e block

    const float* kb = g_k + (long)(b * SEQ + c * CHUNK) * DIM + h * HD;
    const float* vb = g_v + (long)(b * SEQ + c * CHUNK) * DIM + h * HD;

    float acc[4][4] = {};

    for (int sb = 0; sb < CHUNK; sb += 64) {
        __syncthreads();
        #pragma unroll
        for (int r = 0; r < 4; ++r) {
            int idx = t + 256 * r;
            int row = idx >> 4;
            int c4  = (idx & 15) * 4;
            long g  = (long)(sb + row) * DIM + c4;
            *(float4*)&ks[row][c4] = *(const float4*)(kb + g);
            *(float4*)&vs[row][c4] = *(const float4*)(vb + g);
        }
        __syncthreads();

        #pragma unroll 16
        for (int s = 0; s < 64; ++s) {
            float4 kf = *(const float4*)&ks[s][td * 4];
            float4 vf = *(const float4*)&vs[s][te * 4];
            float kr[4] = {kf.x, kf.y, kf.z, kf.w};
            float vr[4] = {vf.x, vf.y, vf.z, vf.w};
            #pragma unroll
            for (int i = 0; i < 4; ++i)
                #pragma unroll
                for (int j = 0; j < 4; ++j)
                    acc[i][j] += kr[i] * vr[j];
        }
    }

    float* out = g_kvp + ((long)((b * NH + h) * NC + c)) * HD * HD
                       + (td * 4) * HD + te * 4;
    #pragma unroll
    for (int i = 0; i < 4; ++i)
        *(float4*)(out + i * HD) = make_float4(acc[i][0], acc[i][1], acc[i][2], acc[i][3]);
}

// ---------------------------------------------------------------------------
// Fused readout matrix:
//   MT[b, j, h*64+d] = sum_e kv[b,h,d,e] * o_w[j, h*64+e]
// where kv = sum over NC partials. Then y[b] = q[b] @ MT[b]^T + o_b becomes the
// same GEMM template as QKV (B matrix is [N=1024 rows, K contiguous]).
// grid = (DIM/64 j-tiles, NH, BATCH), 256 threads.
// ---------------------------------------------------------------------------
__global__ __launch_bounds__(256)
void make_mt(const float* __restrict__ OW)
{
    __shared__ float kvs[64][65];   // [d][e], padded: compute reads stride-65
    __shared__ float ows[64][64];   // [j_local][e]

    const int jt = blockIdx.x, h = blockIdx.y, b = blockIdx.z;
    const int t  = threadIdx.x;
    const int j0 = jt * 64;

    // Sum the NC partials into kvs[d][e] (coalesced gmem, stride-1 smem store)
    const float* pb = g_kvp + (long)((b * NH + h) * NC) * HD * HD;
    #pragma unroll
    for (int r = 0; r < 16; ++r) {
        int idx = t + 256 * r;            // = d*64 + e
        float s = 0.0f;
        #pragma unroll
        for (int c = 0; c < NC; ++c) s += pb[c * HD * HD + idx];
        kvs[idx >> 6][idx & 63] = s;
    }
    // Load o_w tile: rows j0..j0+63, cols h*64..h*64+63
    #pragma unroll
    for (int r = 0; r < 16; ++r) {
        int idx = t + 256 * r;
        int row = idx >> 6, e = idx & 63;
        ows[row][e] = OW[(long)(j0 + row) * DIM + h * HD + e];
    }
    __syncthreads();

    const int d  = t & 63;            // conflict-free via kvs padding
    const int rb = (t >> 6) * 16;     // 16 j-rows per thread
    float acc[16] = {};

    #pragma unroll 4
    for (int e = 0; e < 64; ++e) {
        float kd = kvs[d][e];
        #pragma unroll
        for (int jj = 0; jj < 16; ++jj)
            acc[jj] += ows[rb + jj][e] * kd;   // ows read is warp-broadcast
    }

    float* mt = g_mt + (long)b * DIM * DIM + h * HD + d;
    #pragma unroll
    for (int jj = 0; jj < 16; ++jj)
        mt[(long)(j0 + rb + jj) * DIM] = acc[jj];   // coalesced across threads
}

// ---------------------------------------------------------------------------
// Launch
// ---------------------------------------------------------------------------
extern "C" void kernel_launch(void* const* d_in, const int* in_sizes, int n_in,
                              void* d_out, int out_size)
{
    (void)in_sizes; (void)n_in; (void)out_size;
    const float* x  = (const float*)d_in[0];
    const float* qw = (const float*)d_in[1];
    const float* qb = (const float*)d_in[2];
    const float* kw = (const float*)d_in[3];
    const float* kb = (const float*)d_in[4];
    const float* vw = (const float*)d_in[5];
    const float* vb = (const float*)d_in[6];
    const float* ow = (const float*)d_in[7];
    const float* ob = (const float*)d_in[8];
    float* y = (float*)d_out;

    const int MROWS = BATCH * SEQ;   // 16384

    // 1-3) QKV projections: q,k get ReLU epilogue
    dim3 gQKV(DIM / 128, MROWS / 128, 1);
    gemm_bias<true ><<<gQKV, 256>>>(x, 0, qw, 0, qb, nullptr, 1, MROWS, DIM, DIM, 0, 0, 0);
    gemm_bias<true ><<<gQKV, 256>>>(x, 0, kw, 0, kb, nullptr, 2, MROWS, DIM, DIM, 0, 0, 0);
    gemm_bias<false><<<gQKV, 256>>>(x, 0, vw, 0, vb, nullptr, 3, MROWS, DIM, DIM, 0, 0, 0);

    // 4) kv state partials per (b,h,chunk)
    kv_partial<<<dim3(NC, NH, BATCH), 256>>>();

    // 5) fold o_w into the kv state: MT[b] (stored [j][k], K contiguous)
    make_mt<<<dim3(DIM / 64, NH, BATCH), 256>>>(ow);

    // 6) y[b] = q[b] @ MT[b]^T + o_b   (per-batch via blockIdx.z strides)
    gemm_bias<false><<<dim3(DIM / 128, SEQ / 128, BATCH), 256>>>(
        nullptr, 1, nullptr, 4, ob, y, 0,
        SEQ, DIM, DIM,
        (long)SEQ * DIM, (long)DIM * DIM, (long)SEQ * DIM);
}

// round 3
// speedup vs baseline: 2.3311x; 2.3311x over previous
#include <cuda_runtime.h>
#include <cuda_bf16.h>
#include <cstdint>

// Problem constants
#define BATCH 4
#define SEQ   4096
#define DIM   1024
#define NH    16
#define HD    64
#define KVC   32              // split-S chunks for kv accumulation
#define KCH   (SEQ / KVC)     // 128

// GEMM tile config (mma.sync path — no tcgen05 on bare sm_100 target)
#define GK      1024
#define TM      128
#define TN      128
#define BK      32                   // K elements per chunk
#define NCHUNK  (GK / BK)            // 32
#define RS      40                   // smem row stride in bf16 (32 data + 8 pad) = 80B
#define TILE_B  (128 * RS * 2)       // 10240 bytes per tile
#define STAGE_B (4 * TILE_B)         // Ah, Al, Bh, Bl = 40960 bytes
#define NSTAGE  4
#define GSMEM   (NSTAGE * STAGE_B)   // 163840 bytes

// ---------------------------------------------------------------------------
// Scratch (static __device__ globals; allocation-free per harness rules)
// ---------------------------------------------------------------------------
__device__ __nv_bfloat16 g_xh[BATCH * SEQ * DIM];
__device__ __nv_bfloat16 g_xl[BATCH * SEQ * DIM];
__device__ __nv_bfloat16 g_qwh[DIM * DIM], g_qwl[DIM * DIM];
__device__ __nv_bfloat16 g_kwh[DIM * DIM], g_kwl[DIM * DIM];
__device__ __nv_bfloat16 g_vwh[DIM * DIM], g_vwl[DIM * DIM];
__device__ __nv_bfloat16 g_qh[BATCH * SEQ * DIM], g_ql[BATCH * SEQ * DIM];
__device__ float g_k[BATCH * SEQ * DIM];
__device__ float g_v[BATCH * SEQ * DIM];
__device__ float g_kvp[BATCH * NH * KVC * HD * HD];
__device__ __nv_bfloat16 g_mth[BATCH * DIM * DIM], g_mtl[BATCH * DIM * DIM];

// ---------------------------------------------------------------------------
// PTX helpers (sm_80+ compatible only: cp.async + mma.sync)
// ---------------------------------------------------------------------------
__device__ __forceinline__ uint32_t smem_u32(const void* p) {
    uint32_t a;
    asm("{ .reg .u64 t; cvta.to.shared.u64 t, %1; cvt.u32.u64 %0, t; }" : "=r"(a) : "l"(p));
    return a;
}

#define CP_ASYNC16(s, g) asm volatile("cp.async.cg.shared.global [%0], [%1], 16;" :: "r"(s), "l"(g))
#define CP_COMMIT()      asm volatile("cp.async.commit_group;" ::: "memory")
#define CP_WAIT2()       asm volatile("cp.async.wait_group 2;" ::: "memory")

// D += A * B  (m16n8k16, bf16 in, f32 accum)
__device__ __forceinline__ void mma16816(float* c, const uint32_t* a, const uint32_t* b) {
    asm volatile(
        "mma.sync.aligned.m16n8k16.row.col.f32.bf16.bf16.f32 "
        "{%0,%1,%2,%3}, {%4,%5,%6,%7}, {%8,%9}, {%0,%1,%2,%3};"
        : "+f"(c[0]), "+f"(c[1]), "+f"(c[2]), "+f"(c[3])
        : "r"(a[0]), "r"(a[1]), "r"(a[2]), "r"(a[3]), "r"(b[0]), "r"(b[1]));
}

// bf16 split helpers
__device__ __forceinline__ uint32_t pack2bf(float lo_v, float hi_v) {
    uint32_t r;
    asm("cvt.rn.bf16x2.f32 %0, %1, %2;" : "=r"(r) : "f"(hi_v), "f"(lo_v));
    return r;
}
__device__ __forceinline__ float bf16_rn(float v) {
    __nv_bfloat16 b = __float2bfloat16(v);
    return __bfloat162float(b);
}

// ---------------------------------------------------------------------------
// Split kernel: fp32 -> (bf16 hi, bf16 lo)
// ---------------------------------------------------------------------------
__global__ void split_f32_kernel(const float* __restrict__ s,
                                 __nv_bfloat16* __restrict__ ho,
                                 __nv_bfloat16* __restrict__ lo, long n)
{
    long i = ((long)blockIdx.x * blockDim.x + threadIdx.x) * 4;
    if (i >= n) return;
    float4 v = *(const float4*)(s + i);
    float hx = bf16_rn(v.x), hy = bf16_rn(v.y), hz = bf16_rn(v.z), hw = bf16_rn(v.w);
    uint2 hp = make_uint2(pack2bf(v.x, v.y), pack2bf(v.z, v.w));
    uint2 lp = make_uint2(pack2bf(v.x - hx, v.y - hy), pack2bf(v.z - hz, v.w - hw));
    *(uint2*)(ho + i) = hp;
    *(uint2*)(lo + i) = lp;
}

// ---------------------------------------------------------------------------
// HMMA GEMM: C[M,N] = A[M,K] * B[N,K]^T + bias[N], A,B pre-split bf16 (hi,lo);
// computes Ah*Bh + Ah*Bl + Al*Bh. MODE 0: fp32 out. MODE 1: split bf16 out.
// 256 threads, 128x128 tile, BK=32, 4-stage cp.async pipeline.
// ---------------------------------------------------------------------------
template <int MODE, bool RELU>
__global__ __launch_bounds__(256, 1)
void gemm_bf16x3(const __nv_bfloat16* __restrict__ Ah, const __nv_bfloat16* __restrict__ Al,
                 const __nv_bfloat16* __restrict__ Bh, const __nv_bfloat16* __restrict__ Bl,
                 const float* __restrict__ bias,
                 float* __restrict__ outF,
                 __nv_bfloat16* __restrict__ outH, __nv_bfloat16* __restrict__ outL,
                 long sA, long sB, long sC)
{
    extern __shared__ char smem[];
    const uint32_t smem_addr = smem_u32(smem);

    const int tid  = threadIdx.x;
    const int wid  = tid >> 5;
    const int lane = tid & 31;
    const int z    = blockIdx.z;
    const int m0   = blockIdx.y * TM;
    const int n0   = blockIdx.x * TN;

    Ah += (long)z * sA; Al += (long)z * sA;
    Bh += (long)z * sB; Bl += (long)z * sB;

    // Per-thread cp.async geometry: 2 (row,chunk) slots per tile
    const int r0 = (tid + 0)   >> 2, c0ck = (tid + 0)   & 3;
    const int r1 = (tid + 256) >> 2, c1ck = (tid + 256) & 3;
    const uint32_t so0 = (uint32_t)(r0 * RS + c0ck * 8) * 2;
    const uint32_t so1 = (uint32_t)(r1 * RS + c1ck * 8) * 2;
    const long ga0 = (long)(m0 + r0) * GK + c0ck * 8;
    const long ga1 = (long)(m0 + r1) * GK + c1ck * 8;
    const long gb0 = (long)(n0 + r0) * GK + c0ck * 8;
    const long gb1 = (long)(n0 + r1) * GK + c1ck * 8;

    auto load_stage = [&](int kt, int buf) {
        const uint32_t sb = smem_addr + buf * STAGE_B;
        const long ko = (long)kt * BK;
        CP_ASYNC16(sb + 0 * TILE_B + so0, Ah + ga0 + ko);
        CP_ASYNC16(sb + 0 * TILE_B + so1, Ah + ga1 + ko);
        CP_ASYNC16(sb + 1 * TILE_B + so0, Al + ga0 + ko);
        CP_ASYNC16(sb + 1 * TILE_B + so1, Al + ga1 + ko);
        CP_ASYNC16(sb + 2 * TILE_B + so0, Bh + gb0 + ko);
        CP_ASYNC16(sb + 2 * TILE_B + so1, Bh + gb1 + ko);
        CP_ASYNC16(sb + 3 * TILE_B + so0, Bl + gb0 + ko);
        CP_ASYNC16(sb + 3 * TILE_B + so1, Bl + gb1 + ko);
    };

    // Prologue: fill stages 0,1,2 of the 4-stage ring
    load_stage(0, 0); CP_COMMIT();
    load_stage(1, 1); CP_COMMIT();
    load_stage(2, 2); CP_COMMIT();

    // Warp tiling: 2x4 warp grid, each warp 64x32
    const int wm  = (wid >> 2) * 64;
    const int wn  = (wid & 3) * 32;
    const int lr  = lane >> 2;
    const int lc2 = (lane & 3) * 2;

    float acc[4][4][4] = {};

    for (int kt = 0; kt < NCHUNK; ++kt) {
        CP_WAIT2();              // stage kt resident (always-commit keeps count uniform)
        __syncthreads();         // also: all warps finished compute(kt-1)

        // Refill ring slot (kt+3)%4 == (kt-1)%4 — consumed at kt-1, safe now
        if (kt + 3 < NCHUNK) load_stage(kt + 3, (kt + 3) & 3);
        CP_COMMIT();

        const char* S = smem + (kt & 3) * STAGE_B;

        #pragma unroll
        for (int ks2 = 0; ks2 < 2; ++ks2) {
            const int ks = ks2 * 16;
            uint32_t ah[4][4], al2[4][4], bh[4][2], bl2[4][2];

            #pragma unroll
            for (int mt = 0; mt < 4; ++mt) {
                const int r = wm + mt * 16 + lr;
                const uint32_t o00 = (uint32_t)((r)     * RS + ks + lc2) * 2;
                const uint32_t o10 = (uint32_t)((r + 8) * RS + ks + lc2) * 2;
                ah[mt][0]  = *(const uint32_t*)(S + o00);
                ah[mt][1]  = *(const uint32_t*)(S + o10);
                ah[mt][2]  = *(const uint32_t*)(S + o00 + 16);
                ah[mt][3]  = *(const uint32_t*)(S + o10 + 16);
                al2[mt][0] = *(const uint32_t*)(S + TILE_B + o00);
                al2[mt][1] = *(const uint32_t*)(S + TILE_B + o10);
                al2[mt][2] = *(const uint32_t*)(S + TILE_B + o00 + 16);
                al2[mt][3] = *(const uint32_t*)(S + TILE_B + o10 + 16);
            }
            #pragma unroll
            for (int nt = 0; nt < 4; ++nt) {
                const int n = wn + nt * 8 + lr;
                const uint32_t ob = (uint32_t)(n * RS + ks + lc2) * 2;
                bh[nt][0]  = *(const uint32_t*)(S + 2 * TILE_B + ob);
                bh[nt][1]  = *(const uint32_t*)(S + 2 * TILE_B + ob + 16);
                bl2[nt][0] = *(const uint32_t*)(S + 3 * TILE_B + ob);
                bl2[nt][1] = *(const uint32_t*)(S + 3 * TILE_B + ob + 16);
            }

            #pragma unroll
            for (int mt = 0; mt < 4; ++mt)
                #pragma unroll
                for (int nt = 0; nt < 4; ++nt) {
                    mma16816(acc[mt][nt], ah[mt],  bh[nt]);
                    mma16816(acc[mt][nt], ah[mt],  bl2[nt]);
                    mma16816(acc[mt][nt], al2[mt], bh[nt]);
                }
        }
    }

    // Epilogue: each thread owns (mt,nt) 2x2 f32 quads at known (row,col)
    #pragma unroll
    for (int mt = 0; mt < 4; ++mt) {
        #pragma unroll
        for (int nt = 0; nt < 4; ++nt) {
            const int row = m0 + wm + mt * 16 + lr;
            const int col = n0 + wn + nt * 8 + lc2;
            const float2 bv = *(const float2*)(bias + col);
            float v00 = acc[mt][nt][0] + bv.x, v01 = acc[mt][nt][1] + bv.y;
            float v10 = acc[mt][nt][2] + bv.x, v11 = acc[mt][nt][3] + bv.y;
            if (RELU) {
                v00 = fmaxf(v00, 0.f); v01 = fmaxf(v01, 0.f);
                v10 = fmaxf(v10, 0.f); v11 = fmaxf(v11, 0.f);
            }
            if (MODE == 0) {
                float* p = outF + (long)z * sC + (long)row * DIM + col;
                *(float2*)p                = make_float2(v00, v01);
                *(float2*)(p + 8L * DIM)   = make_float2(v10, v11);
            } else {
                const long o = (long)row * DIM + col;
                float h00 = bf16_rn(v00), h01 = bf16_rn(v01);
                float h10 = bf16_rn(v10), h11 = bf16_rn(v11);
                *(uint32_t*)(outH + o)            = pack2bf(v00, v01);
                *(uint32_t*)(outH + o + 8L * DIM) = pack2bf(v10, v11);
                *(uint32_t*)(outL + o)            = pack2bf(v00 - h00, v01 - h01);
                *(uint32_t*)(outL + o + 8L * DIM) = pack2bf(v10 - h10, v11 - h11);
            }
        }
    }
}

// ---------------------------------------------------------------------------
// kv partials: P[b,h,c,d,e] = sum_{s in chunk} k[b,s,h,d] * v[b,s,h,e]
// ---------------------------------------------------------------------------
__global__ __launch_bounds__(256)
void kv_partial()
{
    __shared__ float ks[64][64];
    __shared__ float vs[64][64];

    const int c = blockIdx.x, hh = blockIdx.y, b = blockIdx.z;
    const int t  = threadIdx.x;
    const int td = t >> 4;
    const int te = t & 15;

    const float* kb = g_k + (long)(b * SEQ + c * KCH) * DIM + hh * HD;
    const float* vb = g_v + (long)(b * SEQ + c * KCH) * DIM + hh * HD;

    float acc[4][4] = {};

    for (int sbk = 0; sbk < KCH; sbk += 64) {
        __syncthreads();
        #pragma unroll
        for (int r = 0; r < 4; ++r) {
            int idx = t + 256 * r;
            int row = idx >> 4;
            int c4  = (idx & 15) * 4;
            long g  = (long)(sbk + row) * DIM + c4;
            *(float4*)&ks[row][c4] = *(const float4*)(kb + g);
            *(float4*)&vs[row][c4] = *(const float4*)(vb + g);
        }
        __syncthreads();

        #pragma unroll 16
        for (int s = 0; s < 64; ++s) {
            float4 kf = *(const float4*)&ks[s][td * 4];
            float4 vf = *(const float4*)&vs[s][te * 4];
            float kr[4] = {kf.x, kf.y, kf.z, kf.w};
            float vr[4] = {vf.x, vf.y, vf.z, vf.w};
            #pragma unroll
            for (int i = 0; i < 4; ++i)
                #pragma unroll
                for (int j = 0; j < 4; ++j)
                    acc[i][j] += kr[i] * vr[j];
        }
    }

    float* out = g_kvp + ((long)((b * NH + hh) * KVC + c)) * HD * HD
                       + (td * 4) * HD + te * 4;
    #pragma unroll
    for (int i = 0; i < 4; ++i)
        *(float4*)(out + i * HD) = make_float4(acc[i][0], acc[i][1], acc[i][2], acc[i][3]);
}

// ---------------------------------------------------------------------------
// MT[b, j, h*64+d] = sum_e kv[b,h,d,e] * o_w[j, h*64+e]; output split to bf16
// ---------------------------------------------------------------------------
__global__ __launch_bounds__(256)
void make_mt(const float* __restrict__ OW)
{
    __shared__ float kvs[64][65];
    __shared__ float ows[64][64];

    const int jt = blockIdx.x, hh = blockIdx.y, b = blockIdx.z;
    const int t  = threadIdx.x;
    const int j0 = jt * 64;

    const float* pb = g_kvp + (long)((b * NH + hh) * KVC) * HD * HD;
    #pragma unroll
    for (int r = 0; r < 16; ++r) {
        int idx = t + 256 * r;
        float s = 0.0f;
        #pragma unroll
        for (int c = 0; c < KVC; ++c) s += pb[c * HD * HD + idx];
        kvs[idx >> 6][idx & 63] = s;
    }
    #pragma unroll
    for (int r = 0; r < 16; ++r) {
        int idx = t + 256 * r;
        int row = idx >> 6, e = idx & 63;
        ows[row][e] = OW[(long)(j0 + row) * DIM + hh * HD + e];
    }
    __syncthreads();

    const int d  = t & 63;
    const int rb = (t >> 6) * 16;
    float acc[16] = {};

    #pragma unroll 4
    for (int e = 0; e < 64; ++e) {
        float kd = kvs[d][e];
        #pragma unroll
        for (int jj = 0; jj < 16; ++jj)
            acc[jj] += ows[rb + jj][e] * kd;
    }

    long base = (long)b * DIM * DIM + hh * HD + d;
    #pragma unroll
    for (int jj = 0; jj < 16; ++jj) {
        float v = acc[jj];
        float hv = bf16_rn(v);
        long idx = base + (long)(j0 + rb + jj) * DIM;
        g_mth[idx] = __float2bfloat16(v);
        g_mtl[idx] = __float2bfloat16(v - hv);
    }
}

// ---------------------------------------------------------------------------
// Launch
// ---------------------------------------------------------------------------
template <typename T>
static T* sym_addr(const void* sym) {
    void* p = nullptr;
    cudaGetSymbolAddress(&p, sym);
    return (T*)p;
}

extern "C" void kernel_launch(void* const* d_in, const int* in_sizes, int n_in,
                              void* d_out, int out_size)
{
    (void)in_sizes; (void)n_in; (void)out_size;
    const float* x  = (const float*)d_in[0];
    const float* qw = (const float*)d_in[1];
    const float* qb = (const float*)d_in[2];
    const float* kw = (const float*)d_in[3];
    const float* kb = (const float*)d_in[4];
    const float* vw = (const float*)d_in[5];
    const float* vb = (const float*)d_in[6];
    const float* ow = (const float*)d_in[7];
    const float* ob = (const float*)d_in[8];
    float* y = (float*)d_out;

    __nv_bfloat16* xh  = sym_addr<__nv_bfloat16>(g_xh);
    __nv_bfloat16* xl  = sym_addr<__nv_bfloat16>(g_xl);
    __nv_bfloat16* qwh = sym_addr<__nv_bfloat16>(g_qwh);
    __nv_bfloat16* qwl = sym_addr<__nv_bfloat16>(g_qwl);
    __nv_bfloat16* kwh = sym_addr<__nv_bfloat16>(g_kwh);
    __nv_bfloat16* kwl = sym_addr<__nv_bfloat16>(g_kwl);
    __nv_bfloat16* vwh = sym_addr<__nv_bfloat16>(g_vwh);
    __nv_bfloat16* vwl = sym_addr<__nv_bfloat16>(g_vwl);
    __nv_bfloat16* qh  = sym_addr<__nv_bfloat16>(g_qh);
    __nv_bfloat16* ql  = sym_addr<__nv_bfloat16>(g_ql);
    float*         gk  = sym_addr<float>(g_k);
    float*         gv  = sym_addr<float>(g_v);
    __nv_bfloat16* mth = sym_addr<__nv_bfloat16>(g_mth);
    __nv_bfloat16* mtl = sym_addr<__nv_bfloat16>(g_mtl);

    cudaFuncSetAttribute(gemm_bf16x3<0, false>, cudaFuncAttributeMaxDynamicSharedMemorySize, GSMEM);
    cudaFuncSetAttribute(gemm_bf16x3<0, true >, cudaFuncAttributeMaxDynamicSharedMemorySize, GSMEM);
    cudaFuncSetAttribute(gemm_bf16x3<1, true >, cudaFuncAttributeMaxDynamicSharedMemorySize, GSMEM);

    const long NX = (long)BATCH * SEQ * DIM;   // 16.7M
    const long NW = (long)DIM * DIM;           // 1M

    // 0) split inputs/weights to bf16 hi/lo
    split_f32_kernel<<<(int)(NX / 4 / 256), 256>>>(x,  xh,  xl,  NX);
    split_f32_kernel<<<(int)(NW / 4 / 256), 256>>>(qw, qwh, qwl, NW);
    split_f32_kernel<<<(int)(NW / 4 / 256), 256>>>(kw, kwh, kwl, NW);
    split_f32_kernel<<<(int)(NW / 4 / 256), 256>>>(vw, vwh, vwl, NW);

    // 1-3) QKV projections on HMMA tensor cores
    dim3 gQKV(DIM / TN, (BATCH * SEQ) / TM, 1);
    gemm_bf16x3<1, true ><<<gQKV, 256, GSMEM>>>(xh, xl, qwh, qwl, qb, nullptr, qh, ql, 0, 0, 0);
    gemm_bf16x3<0, true ><<<gQKV, 256, GSMEM>>>(xh, xl, kwh, kwl, kb, gk, nullptr, nullptr, 0, 0, 0);
    gemm_bf16x3<0, false><<<gQKV, 256, GSMEM>>>(xh, xl, vwh, vwl, vb, gv, nullptr, nullptr, 0, 0, 0);

    // 4) kv state partials
    kv_partial<<<dim3(KVC, NH, BATCH), 256>>>();

    // 5) fold o_w into kv state, split to bf16
    make_mt<<<dim3(DIM / 64, NH, BATCH), 256>>>(ow);

    // 6) y[b] = q[b] @ MT[b]^T + o_b
    gemm_bf16x3<0, false><<<dim3(DIM / TN, SEQ / TM, BATCH), 256, GSMEM>>>(
        qh, ql, mth, mtl, ob, y, nullptr, nullptr,
        (long)SEQ * DIM, (long)DIM * DIM, (long)SEQ * DIM);
}

// round 4
// speedup vs baseline: 2.4749x; 1.0617x over previous
#include <cuda_runtime.h>
#include <cuda_bf16.h>
#include <cstdint>

// Problem constants
#define BATCH 4
#define SEQ   4096
#define DIM   1024
#define NH    16
#define HD    64
#define KVC   32              // split-S chunks for kv accumulation
#define KCH   (SEQ / KVC)     // 128

// GEMM tile config (mma.sync path — no tcgen05 on bare sm_100 target)
#define GK      1024
#define TM      128
#define TN      128
#define BK      32                   // K elements per chunk
#define NCHUNK  (GK / BK)            // 32
#define RS      40                   // smem row stride in bf16 (32 data + 8 pad) = 80B
#define TILE_B  (128 * RS * 2)       // 10240 bytes per tile
#define STAGE_B (4 * TILE_B)         // Ah, Al, Bh, Bl = 40960 bytes
#define NSTAGE  4
#define GSMEM   (NSTAGE * STAGE_B)   // 163840 bytes

// ---------------------------------------------------------------------------
// Scratch (static __device__ globals; allocation-free per harness rules)
// ---------------------------------------------------------------------------
__device__ __nv_bfloat16 g_xh[BATCH * SEQ * DIM];
__device__ __nv_bfloat16 g_xl[BATCH * SEQ * DIM];
__device__ __nv_bfloat16 g_qwh[DIM * DIM], g_qwl[DIM * DIM];
__device__ __nv_bfloat16 g_kwh[DIM * DIM], g_kwl[DIM * DIM];
__device__ __nv_bfloat16 g_vwh[DIM * DIM], g_vwl[DIM * DIM];
__device__ __nv_bfloat16 g_qh[BATCH * SEQ * DIM], g_ql[BATCH * SEQ * DIM];
__device__ float g_k[BATCH * SEQ * DIM];
__device__ float g_v[BATCH * SEQ * DIM];
__device__ float g_kvp[BATCH * NH * KVC * HD * HD];
__device__ __nv_bfloat16 g_mth[BATCH * DIM * DIM], g_mtl[BATCH * DIM * DIM];

// ---------------------------------------------------------------------------
// PTX helpers (sm_80+ compatible only: cp.async + mma.sync + ldmatrix)
// ---------------------------------------------------------------------------
__device__ __forceinline__ uint32_t smem_u32(const void* p) {
    uint32_t a;
    asm("{ .reg .u64 t; cvta.to.shared.u64 t, %1; cvt.u32.u64 %0, t; }" : "=r"(a) : "l"(p));
    return a;
}

#define CP_ASYNC16(s, g) asm volatile("cp.async.cg.shared.global [%0], [%1], 16;" :: "r"(s), "l"(g))
#define CP_COMMIT()      asm volatile("cp.async.commit_group;" ::: "memory")
#define CP_WAIT2()       asm volatile("cp.async.wait_group 2;" ::: "memory")

#define LDSM_X4(r0, r1, r2, r3, a) \
    asm volatile("ldmatrix.sync.aligned.m8n8.x4.shared.b16 {%0,%1,%2,%3}, [%4];" \
                 : "=r"(r0), "=r"(r1), "=r"(r2), "=r"(r3) : "r"(a))

// D += A * B  (m16n8k16, bf16 in, f32 accum)
__device__ __forceinline__ void mma16816(float* c, const uint32_t* a, const uint32_t* b) {
    asm volatile(
        "mma.sync.aligned.m16n8k16.row.col.f32.bf16.bf16.f32 "
        "{%0,%1,%2,%3}, {%4,%5,%6,%7}, {%8,%9}, {%0,%1,%2,%3};"
        : "+f"(c[0]), "+f"(c[1]), "+f"(c[2]), "+f"(c[3])
        : "r"(a[0]), "r"(a[1]), "r"(a[2]), "r"(a[3]), "r"(b[0]), "r"(b[1]));
}

// bf16 split helpers
__device__ __forceinline__ uint32_t pack2bf(float lo_v, float hi_v) {
    uint32_t r;
    asm("cvt.rn.bf16x2.f32 %0, %1, %2;" : "=r"(r) : "f"(hi_v), "f"(lo_v));
    return r;
}
__device__ __forceinline__ float bf16_rn(float v) {
    __nv_bfloat16 b = __float2bfloat16(v);
    return __bfloat162float(b);
}

// ---------------------------------------------------------------------------
// Split kernel: fp32 -> (bf16 hi, bf16 lo)
// ---------------------------------------------------------------------------
__global__ void split_f32_kernel(const float* __restrict__ s,
                                 __nv_bfloat16* __restrict__ ho,
                                 __nv_bfloat16* __restrict__ lo, long n)
{
    long i = ((long)blockIdx.x * blockDim.x + threadIdx.x) * 4;
    if (i >= n) return;
    float4 v = *(const float4*)(s + i);
    float hx = bf16_rn(v.x), hy = bf16_rn(v.y), hz = bf16_rn(v.z), hw = bf16_rn(v.w);
    uint2 hp = make_uint2(pack2bf(v.x, v.y), pack2bf(v.z, v.w));
    uint2 lp = make_uint2(pack2bf(v.x - hx, v.y - hy), pack2bf(v.z - hz, v.w - hw));
    *(uint2*)(ho + i) = hp;
    *(uint2*)(lo + i) = lp;
}

// ---------------------------------------------------------------------------
// HMMA GEMM: C[M,N] = A[M,K] * B[N,K]^T + bias[N], A,B pre-split bf16 (hi,lo);
// computes Ah*Bh + Ah*Bl + Al*Bh. MODE 0: fp32 out. MODE 1: split bf16 out.
// 256 threads, 128x128 tile, BK=32, 4-stage cp.async pipeline, ldmatrix frags.
// ---------------------------------------------------------------------------
template <int MODE, bool RELU>
__global__ __launch_bounds__(256, 1)
void gemm_bf16x3(const __nv_bfloat16* __restrict__ Ah, const __nv_bfloat16* __restrict__ Al,
                 const __nv_bfloat16* __restrict__ Bh, const __nv_bfloat16* __restrict__ Bl,
                 const float* __restrict__ bias,
                 float* __restrict__ outF,
                 __nv_bfloat16* __restrict__ outH, __nv_bfloat16* __restrict__ outL,
                 long sA, long sB, long sC)
{
    extern __shared__ char smem[];
    const uint32_t smem_addr = smem_u32(smem);

    const int tid  = threadIdx.x;
    const int wid  = tid >> 5;
    const int lane = tid & 31;
    const int z    = blockIdx.z;
    const int m0   = blockIdx.y * TM;
    const int n0   = blockIdx.x * TN;

    Ah += (long)z * sA; Al += (long)z * sA;
    Bh += (long)z * sB; Bl += (long)z * sB;

    // Per-thread cp.async geometry: 2 (row,chunk) slots per tile
    const int r0 = (tid + 0)   >> 2, c0ck = (tid + 0)   & 3;
    const int r1 = (tid + 256) >> 2, c1ck = (tid + 256) & 3;
    const uint32_t so0 = (uint32_t)(r0 * RS + c0ck * 8) * 2;
    const uint32_t so1 = (uint32_t)(r1 * RS + c1ck * 8) * 2;
    const long ga0 = (long)(m0 + r0) * GK + c0ck * 8;
    const long ga1 = (long)(m0 + r1) * GK + c1ck * 8;
    const long gb0 = (long)(n0 + r0) * GK + c0ck * 8;
    const long gb1 = (long)(n0 + r1) * GK + c1ck * 8;

    auto load_stage = [&](int kt, int buf) {
        const uint32_t sb = smem_addr + buf * STAGE_B;
        const long ko = (long)kt * BK;
        CP_ASYNC16(sb + 0 * TILE_B + so0, Ah + ga0 + ko);
        CP_ASYNC16(sb + 0 * TILE_B + so1, Ah + ga1 + ko);
        CP_ASYNC16(sb + 1 * TILE_B + so0, Al + ga0 + ko);
        CP_ASYNC16(sb + 1 * TILE_B + so1, Al + ga1 + ko);
        CP_ASYNC16(sb + 2 * TILE_B + so0, Bh + gb0 + ko);
        CP_ASYNC16(sb + 2 * TILE_B + so1, Bh + gb1 + ko);
        CP_ASYNC16(sb + 3 * TILE_B + so0, Bl + gb0 + ko);
        CP_ASYNC16(sb + 3 * TILE_B + so1, Bl + gb1 + ko);
    };

    // Prologue: fill stages 0,1,2 of the 4-stage ring
    load_stage(0, 0); CP_COMMIT();
    load_stage(1, 1); CP_COMMIT();
    load_stage(2, 2); CP_COMMIT();

    // Warp tiling: 2x4 warp grid, each warp 64x32
    const int wm  = (wid >> 2) * 64;
    const int wn  = (wid & 3) * 32;
    const int lr  = lane >> 2;
    const int lc2 = (lane & 3) * 2;

    // ldmatrix per-lane address parts (byte offsets within a tile)
    // A x4: M00(rows0-7,k0-7) M10(rows8-15,k0-7) M01(rows0-7,k8-15) M11(rows8-15,k8-15)
    const uint32_t rA  = lane & 15;               // row within 16-row frag
    const uint32_t kAp = (uint32_t)(lane >> 4) << 4;  // 0 or 16 bytes (k half)
    // B x4: M0(n0-7,k0-7) M1(n0-7,k8-15) M2(n8-15,k0-7) M3(n8-15,k8-15)
    const uint32_t rB  = (lane & 7) + ((lane & 16) >> 1);
    const uint32_t kBp = (uint32_t)(lane & 8) << 1;    // 0 or 16 bytes

    uint32_t offA[4], offB[2];
    #pragma unroll
    for (int mt = 0; mt < 4; ++mt)
        offA[mt] = (uint32_t)(wm + mt * 16 + rA) * (RS * 2) + kAp;
    #pragma unroll
    for (int ntp = 0; ntp < 2; ++ntp)
        offB[ntp] = (uint32_t)(wn + ntp * 16 + rB) * (RS * 2) + kBp;

    float acc[4][4][4] = {};

    for (int kt = 0; kt < NCHUNK; ++kt) {
        CP_WAIT2();              // stage kt resident (always-commit keeps count uniform)
        __syncthreads();         // also: all warps finished compute(kt-1)

        // Refill ring slot (kt+3)%4 == (kt-1)%4 — consumed at kt-1, safe now
        if (kt + 3 < NCHUNK) load_stage(kt + 3, (kt + 3) & 3);
        CP_COMMIT();

        const uint32_t Sb = smem_addr + (kt & 3) * STAGE_B;

        #pragma unroll
        for (int ks2 = 0; ks2 < 2; ++ks2) {
            const uint32_t kb = ks2 * 32;   // 16 k-elements = 32 bytes
            uint32_t ah[4][4], al2[4][4], bh[4][2], bl2[4][2];

            #pragma unroll
            for (int mt = 0; mt < 4; ++mt) {
                const uint32_t aa = Sb + kb + offA[mt];
                LDSM_X4(ah[mt][0],  ah[mt][1],  ah[mt][2],  ah[mt][3],  aa);
                LDSM_X4(al2[mt][0], al2[mt][1], al2[mt][2], al2[mt][3], aa + TILE_B);
            }
            #pragma unroll
            for (int ntp = 0; ntp < 2; ++ntp) {
                const uint32_t ba = Sb + 2 * TILE_B + kb + offB[ntp];
                LDSM_X4(bh[2*ntp][0],  bh[2*ntp][1],  bh[2*ntp+1][0],  bh[2*ntp+1][1],  ba);
                LDSM_X4(bl2[2*ntp][0], bl2[2*ntp][1], bl2[2*ntp+1][0], bl2[2*ntp+1][1], ba + TILE_B);
            }

            #pragma unroll
            for (int mt = 0; mt < 4; ++mt)
                #pragma unroll
                for (int nt = 0; nt < 4; ++nt) {
                    mma16816(acc[mt][nt], ah[mt],  bh[nt]);
                    mma16816(acc[mt][nt], ah[mt],  bl2[nt]);
                    mma16816(acc[mt][nt], al2[mt], bh[nt]);
                }
        }
    }

    // Epilogue: each thread owns (mt,nt) 2x2 f32 quads at known (row,col)
    #pragma unroll
    for (int mt = 0; mt < 4; ++mt) {
        #pragma unroll
        for (int nt = 0; nt < 4; ++nt) {
            const int row = m0 + wm + mt * 16 + lr;
            const int col = n0 + wn + nt * 8 + lc2;
            const float2 bv = *(const float2*)(bias + col);
            float v00 = acc[mt][nt][0] + bv.x, v01 = acc[mt][nt][1] + bv.y;
            float v10 = acc[mt][nt][2] + bv.x, v11 = acc[mt][nt][3] + bv.y;
            if (RELU) {
                v00 = fmaxf(v00, 0.f); v01 = fmaxf(v01, 0.f);
                v10 = fmaxf(v10, 0.f); v11 = fmaxf(v11, 0.f);
            }
            if (MODE == 0) {
                float* p = outF + (long)z * sC + (long)row * DIM + col;
                *(float2*)p                = make_float2(v00, v01);
                *(float2*)(p + 8L * DIM)   = make_float2(v10, v11);
            } else {
                const long o = (long)row * DIM + col;
                float h00 = bf16_rn(v00), h01 = bf16_rn(v01);
                float h10 = bf16_rn(v10), h11 = bf16_rn(v11);
                *(uint32_t*)(outH + o)            = pack2bf(v00, v01);
                *(uint32_t*)(outH + o + 8L * DIM) = pack2bf(v10, v11);
                *(uint32_t*)(outL + o)            = pack2bf(v00 - h00, v01 - h01);
                *(uint32_t*)(outL + o + 8L * DIM) = pack2bf(v10 - h10, v11 - h11);
            }
        }
    }
}

// ---------------------------------------------------------------------------
// kv partials: P[b,h,c,d,e] = sum_{s in chunk} k[b,s,h,d] * v[b,s,h,e]
// ---------------------------------------------------------------------------
__global__ __launch_bounds__(256)
void kv_partial()
{
    __shared__ float ks[64][64];
    __shared__ float vs[64][64];

    const int c = blockIdx.x, hh = blockIdx.y, b = blockIdx.z;
    const int t  = threadIdx.x;
    const int td = t >> 4;
    const int te = t & 15;

    const float* kb = g_k + (long)(b * SEQ + c * KCH) * DIM + hh * HD;
    const float* vb = g_v + (long)(b * SEQ + c * KCH) * DIM + hh * HD;

    float acc[4][4] = {};

    for (int sbk = 0; sbk < KCH; sbk += 64) {
        __syncthreads();
        #pragma unroll
        for (int r = 0; r < 4; ++r) {
            int idx = t + 256 * r;
            int row = idx >> 4;
            int c4  = (idx & 15) * 4;
            long g  = (long)(sbk + row) * DIM + c4;
            *(float4*)&ks[row][c4] = *(const float4*)(kb + g);
            *(float4*)&vs[row][c4] = *(const float4*)(vb + g);
        }
        __syncthreads();

        #pragma unroll 16
        for (int s = 0; s < 64; ++s) {
            float4 kf = *(const float4*)&ks[s][td * 4];
            float4 vf = *(const float4*)&vs[s][te * 4];
            float kr[4] = {kf.x, kf.y, kf.z, kf.w};
            float vr[4] = {vf.x, vf.y, vf.z, vf.w};
            #pragma unroll
            for (int i = 0; i < 4; ++i)
                #pragma unroll
                for (int j = 0; j < 4; ++j)
                    acc[i][j] += kr[i] * vr[j];
        }
    }

    float* out = g_kvp + ((long)((b * NH + hh) * KVC + c)) * HD * HD
                       + (td * 4) * HD + te * 4;
    #pragma unroll
    for (int i = 0; i < 4; ++i)
        *(float4*)(out + i * HD) = make_float4(acc[i][0], acc[i][1], acc[i][2], acc[i][3]);
}

// ---------------------------------------------------------------------------
// MT[b, j, h*64+d] = sum_e kv[b,h,d,e] * o_w[j, h*64+e]; output split to bf16
// ---------------------------------------------------------------------------
__global__ __launch_bounds__(256)
void make_mt(const float* __restrict__ OW)
{
    __shared__ float kvs[64][65];
    __shared__ float ows[64][64];

    const int jt = blockIdx.x, hh = blockIdx.y, b = blockIdx.z;
    const int t  = threadIdx.x;
    const int j0 = jt * 64;

    const float* pb = g_kvp + (long)((b * NH + hh) * KVC) * HD * HD;
    #pragma unroll
    for (int r = 0; r < 16; ++r) {
        int idx = t + 256 * r;
        float s = 0.0f;
        #pragma unroll
        for (int c = 0; c < KVC; ++c) s += pb[c * HD * HD + idx];
        kvs[idx >> 6][idx & 63] = s;
    }
    #pragma unroll
    for (int r = 0; r < 16; ++r) {
        int idx = t + 256 * r;
        int row = idx >> 6, e = idx & 63;
        ows[row][e] = OW[(long)(j0 + row) * DIM + hh * HD + e];
    }
    __syncthreads();

    const int d  = t & 63;
    const int rb = (t >> 6) * 16;
    float acc[16] = {};

    #pragma unroll 4
    for (int e = 0; e < 64; ++e) {
        float kd = kvs[d][e];
        #pragma unroll
        for (int jj = 0; jj < 16; ++jj)
            acc[jj] += ows[rb + jj][e] * kd;
    }

    long base = (long)b * DIM * DIM + hh * HD + d;
    #pragma unroll
    for (int jj = 0; jj < 16; ++jj) {
        float v = acc[jj];
        float hv = bf16_rn(v);
        long idx = base + (long)(j0 + rb + jj) * DIM;
        g_mth[idx] = __float2bfloat16(v);
        g_mtl[idx] = __float2bfloat16(v - hv);
    }
}

// ---------------------------------------------------------------------------
// Launch
// ---------------------------------------------------------------------------
template <typename T>
static T* sym_addr(const void* sym) {
    void* p = nullptr;
    cudaGetSymbolAddress(&p, sym);
    return (T*)p;
}

extern "C" void kernel_launch(void* const* d_in, const int* in_sizes, int n_in,
                              void* d_out, int out_size)
{
    (void)in_sizes; (void)n_in; (void)out_size;
    const float* x  = (const float*)d_in[0];
    const float* qw = (const float*)d_in[1];
    const float* qb = (const float*)d_in[2];
    const float* kw = (const float*)d_in[3];
    const float* kb = (const float*)d_in[4];
    const float* vw = (const float*)d_in[5];
    const float* vb = (const float*)d_in[6];
    const float* ow = (const float*)d_in[7];
    const float* ob = (const float*)d_in[8];
    float* y = (float*)d_out;

    __nv_bfloat16* xh  = sym_addr<__nv_bfloat16>(g_xh);
    __nv_bfloat16* xl  = sym_addr<__nv_bfloat16>(g_xl);
    __nv_bfloat16* qwh = sym_addr<__nv_bfloat16>(g_qwh);
    __nv_bfloat16* qwl = sym_addr<__nv_bfloat16>(g_qwl);
    __nv_bfloat16* kwh = sym_addr<__nv_bfloat16>(g_kwh);
    __nv_bfloat16* kwl = sym_addr<__nv_bfloat16>(g_kwl);
    __nv_bfloat16* vwh = sym_addr<__nv_bfloat16>(g_vwh);
    __nv_bfloat16* vwl = sym_addr<__nv_bfloat16>(g_vwl);
    __nv_bfloat16* qh  = sym_addr<__nv_bfloat16>(g_qh);
    __nv_bfloat16* ql  = sym_addr<__nv_bfloat16>(g_ql);
    float*         gk  = sym_addr<float>(g_k);
    float*         gv  = sym_addr<float>(g_v);
    __nv_bfloat16* mth = sym_addr<__nv_bfloat16>(g_mth);
    __nv_bfloat16* mtl = sym_addr<__nv_bfloat16>(g_mtl);

    cudaFuncSetAttribute(gemm_bf16x3<0, false>, cudaFuncAttributeMaxDynamicSharedMemorySize, GSMEM);
    cudaFuncSetAttribute(gemm_bf16x3<0, true >, cudaFuncAttributeMaxDynamicSharedMemorySize, GSMEM);
    cudaFuncSetAttribute(gemm_bf16x3<1, true >, cudaFuncAttributeMaxDynamicSharedMemorySize, GSMEM);

    const long NX = (long)BATCH * SEQ * DIM;   // 16.7M
    const long NW = (long)DIM * DIM;           // 1M

    // 0) split inputs/weights to bf16 hi/lo
    split_f32_kernel<<<(int)(NX / 4 / 256), 256>>>(x,  xh,  xl,  NX);
    split_f32_kernel<<<(int)(NW / 4 / 256), 256>>>(qw, qwh, qwl, NW);
    split_f32_kernel<<<(int)(NW / 4 / 256), 256>>>(kw, kwh, kwl, NW);
    split_f32_kernel<<<(int)(NW / 4 / 256), 256>>>(vw, vwh, vwl, NW);

    // 1-3) QKV projections on HMMA tensor cores
    dim3 gQKV(DIM / TN, (BATCH * SEQ) / TM, 1);
    gemm_bf16x3<1, true ><<<gQKV, 256, GSMEM>>>(xh, xl, qwh, qwl, qb, nullptr, qh, ql, 0, 0, 0);
    gemm_bf16x3<0, true ><<<gQKV, 256, GSMEM>>>(xh, xl, kwh, kwl, kb, gk, nullptr, nullptr, 0, 0, 0);
    gemm_bf16x3<0, false><<<gQKV, 256, GSMEM>>>(xh, xl, vwh, vwl, vb, gv, nullptr, nullptr, 0, 0, 0);

    // 4) kv state partials
    kv_partial<<<dim3(KVC, NH, BATCH), 256>>>();

    // 5) fold o_w into kv state, split to bf16
    make_mt<<<dim3(DIM / 64, NH, BATCH), 256>>>(ow);

    // 6) y[b] = q[b] @ MT[b]^T + o_b
    gemm_bf16x3<0, false><<<dim3(DIM / TN, SEQ / TM, BATCH), 256, GSMEM>>>(
        qh, ql, mth, mtl, ob, y, nullptr, nullptr,
        (long)SEQ * DIM, (long)DIM * DIM, (long)SEQ * DIM);
}